// round 4
// baseline (speedup 1.0000x reference)
#include <cuda_runtime.h>
#include <cuda_bf16.h>
#include <math.h>

#define B_N 8192
#define D_K 512
#define NCLS 100
#define MAXP 256
#define NT 64                       // 8192 / 128 tiles per dim
#define INV_TEMP 14.285714285714286f

// -------- static scratch (no allocations allowed) --------
__device__ float g_P[NT][B_N];        // per-(colTile,row) partial sums of exp (2 MB)
__device__ float g_pos[B_N * MAXP];   // same-label logits, slot = class rank (8 MB)
__device__ float g_L[B_N];            // base_denom_row (log of diff-label exp-sum)
__device__ float g_rowloss[B_N];
__device__ int   g_lab[B_N];
__device__ int   g_rank[B_N];         // rank of row within its class (deterministic)
__device__ int   g_cnt[NCLS];

// ---------------------------------------------------------------------------
// prep: parse labels (int32 or int64), per-class parallel rank assignment.
// Thread c scans all labels (smem broadcast reads); exactly one thread
// matches each j and writes its within-class rank. Deterministic: scan
// order is j-ascending for every class, identical to a serial pass.
// ---------------------------------------------------------------------------
__global__ void prep_kernel(const int* __restrict__ raw) {
    __shared__ int sl[B_N];        // 32 KB
    __shared__ int mode64;
    int tid = threadIdx.x;
    if (tid == 0) {
        // int64 little-endian: every odd 32-bit word is 0 (labels in [0,100))
        int z = 1;
        for (int i = 1; i < 129; i += 2) if (raw[i] != 0) { z = 0; break; }
        mode64 = z;
    }
    __syncthreads();
    int m = mode64;
    for (int i = tid; i < B_N; i += blockDim.x) {
        int v = m ? raw[2 * i] : raw[i];
        sl[i] = v;
        g_lab[i] = v;
    }
    __syncthreads();
    if (tid < NCLS) {
        int c = tid;
        int cnt = 0;
        for (int j = 0; j < B_N; j++) {
            if (sl[j] == c) {            // warp-uniform address -> smem broadcast
                g_rank[j] = cnt;
                cnt++;
            }
        }
        g_cnt[c] = cnt;
    }
}

// ---------------------------------------------------------------------------
// Fused symmetric GEMM + exp-row-reduction + positive-logit scatter.
// Block (tI,tJ) with tI<=tJ computes the 128x128 tile C = Ai . Aj^T / T.
// Double-buffered smem pipeline: prefetch K-step k+1 into registers while
// computing step k; ONE barrier per K-step.
//  - diff-label entries: e=exp(x) accumulated into row sums for both rows
//  - same-label entries (i!=j): stored at deterministic class-rank slots.
// ---------------------------------------------------------------------------
__global__ void __launch_bounds__(256, 2) gemm_kernel(const float* __restrict__ A) {
    int tJ = blockIdx.x, tI = blockIdx.y;
    if (tI > tJ) return;
    bool diag = (tI == tJ);

    __shared__ float As[2][16][128];
    __shared__ float Bs[2][16][128];
    __shared__ int   lbI[128], lbJ[128], rkI[128], rkJ[128];

    int tid = threadIdx.x;
    int tx = tid & 15, ty = tid >> 4;

    if (tid < 128) {
        lbI[tid] = g_lab[tI * 128 + tid];
        rkI[tid] = g_rank[tI * 128 + tid];
        lbJ[tid] = g_lab[tJ * 128 + tid];
        rkJ[tid] = g_rank[tJ * 128 + tid];
    }

    float acc[8][8];
#pragma unroll
    for (int a = 0; a < 8; a++)
#pragma unroll
        for (int b = 0; b < 8; b++) acc[a][b] = 0.f;

    const float* Ai = A + (size_t)tI * 128 * D_K;
    const float* Aj = A + (size_t)tJ * 128 * D_K;

    // each thread loads 2 float4 per matrix per K-step
    int l_row0 = tid >> 2, l_c4_0 = tid & 3;             // idx = tid
    int idx1 = tid + 256;
    int l_row1 = idx1 >> 2, l_c4_1 = idx1 & 3;           // idx = tid+256

    // ---- prologue: load K-step 0 into buffer 0 ----
    {
        float4 va0 = *(const float4*)(Ai + l_row0 * D_K + l_c4_0 * 4);
        float4 vb0 = *(const float4*)(Aj + l_row0 * D_K + l_c4_0 * 4);
        float4 va1 = *(const float4*)(Ai + l_row1 * D_K + l_c4_1 * 4);
        float4 vb1 = *(const float4*)(Aj + l_row1 * D_K + l_c4_1 * 4);
        As[0][l_c4_0 * 4 + 0][l_row0] = va0.x; As[0][l_c4_0 * 4 + 1][l_row0] = va0.y;
        As[0][l_c4_0 * 4 + 2][l_row0] = va0.z; As[0][l_c4_0 * 4 + 3][l_row0] = va0.w;
        Bs[0][l_c4_0 * 4 + 0][l_row0] = vb0.x; Bs[0][l_c4_0 * 4 + 1][l_row0] = vb0.y;
        Bs[0][l_c4_0 * 4 + 2][l_row0] = vb0.z; Bs[0][l_c4_0 * 4 + 3][l_row0] = vb0.w;
        As[0][l_c4_1 * 4 + 0][l_row1] = va1.x; As[0][l_c4_1 * 4 + 1][l_row1] = va1.y;
        As[0][l_c4_1 * 4 + 2][l_row1] = va1.z; As[0][l_c4_1 * 4 + 3][l_row1] = va1.w;
        Bs[0][l_c4_1 * 4 + 0][l_row1] = vb1.x; Bs[0][l_c4_1 * 4 + 1][l_row1] = vb1.y;
        Bs[0][l_c4_1 * 4 + 2][l_row1] = vb1.z; Bs[0][l_c4_1 * 4 + 3][l_row1] = vb1.w;
    }
    __syncthreads();

    int cur = 0;
    for (int k0 = 0; k0 < D_K; k0 += 16) {
        int nxt = cur ^ 1;
        bool has_next = (k0 + 16) < D_K;
        float4 va0, vb0, va1, vb1;
        if (has_next) {
            int kn = k0 + 16;
            va0 = *(const float4*)(Ai + l_row0 * D_K + kn + l_c4_0 * 4);
            vb0 = *(const float4*)(Aj + l_row0 * D_K + kn + l_c4_0 * 4);
            va1 = *(const float4*)(Ai + l_row1 * D_K + kn + l_c4_1 * 4);
            vb1 = *(const float4*)(Aj + l_row1 * D_K + kn + l_c4_1 * 4);
        }
#pragma unroll
        for (int k = 0; k < 16; k++) {
            float a0[8], b0[8];
#pragma unroll
            for (int u = 0; u < 8; u++) a0[u] = As[cur][k][ty * 8 + u];
#pragma unroll
            for (int u = 0; u < 8; u++) b0[u] = Bs[cur][k][tx * 8 + u];
#pragma unroll
            for (int a = 0; a < 8; a++)
#pragma unroll
                for (int b = 0; b < 8; b++)
                    acc[a][b] = fmaf(a0[a], b0[b], acc[a][b]);
        }
        if (has_next) {
            As[nxt][l_c4_0 * 4 + 0][l_row0] = va0.x; As[nxt][l_c4_0 * 4 + 1][l_row0] = va0.y;
            As[nxt][l_c4_0 * 4 + 2][l_row0] = va0.z; As[nxt][l_c4_0 * 4 + 3][l_row0] = va0.w;
            Bs[nxt][l_c4_0 * 4 + 0][l_row0] = vb0.x; Bs[nxt][l_c4_0 * 4 + 1][l_row0] = vb0.y;
            Bs[nxt][l_c4_0 * 4 + 2][l_row0] = vb0.z; Bs[nxt][l_c4_0 * 4 + 3][l_row0] = vb0.w;
            As[nxt][l_c4_1 * 4 + 0][l_row1] = va1.x; As[nxt][l_c4_1 * 4 + 1][l_row1] = va1.y;
            As[nxt][l_c4_1 * 4 + 2][l_row1] = va1.z; As[nxt][l_c4_1 * 4 + 3][l_row1] = va1.w;
            Bs[nxt][l_c4_1 * 4 + 0][l_row1] = vb1.x; Bs[nxt][l_c4_1 * 4 + 1][l_row1] = vb1.y;
            Bs[nxt][l_c4_1 * 4 + 2][l_row1] = vb1.z; Bs[nxt][l_c4_1 * 4 + 3][l_row1] = vb1.w;
        }
        __syncthreads();
        cur = nxt;
    }

    // ---------------- epilogue ----------------
    float rowSum[8], colSum[8];
#pragma unroll
    for (int u = 0; u < 8; u++) { rowSum[u] = 0.f; colSum[u] = 0.f; }

#pragma unroll
    for (int a = 0; a < 8; a++) {
        int i = ty * 8 + a;
        int li = lbI[i];
        int gi = tI * 128 + i;
#pragma unroll
        for (int b = 0; b < 8; b++) {
            int j = tx * 8 + b;
            float x = acc[a][b] * INV_TEMP;
            int lj = lbJ[j];
            if (li != lj) {
                float e = __expf(x);
                rowSum[a] += e;
                colSum[b] += e;
            } else {
                int gj = tJ * 128 + j;
                if (gi != gj) {
                    g_pos[(size_t)gi * MAXP + rkJ[j]] = x;
                    if (!diag) g_pos[(size_t)gj * MAXP + rkI[i]] = x;
                }
            }
        }
    }

    // deterministic in-block reductions (reuse As/Bs as scratch)
    float* redA = &As[0][0][0];   // 2048 floats
    float* redB = &Bs[0][0][0];
#pragma unroll
    for (int a = 0; a < 8; a++) redA[(ty * 8 + a) * 16 + tx] = rowSum[a];
    if (!diag) {
#pragma unroll
        for (int b = 0; b < 8; b++) redB[(tx * 8 + b) * 16 + ty] = colSum[b];
    }
    __syncthreads();
    if (tid < 128) {
        float s = 0.f;
#pragma unroll
        for (int t = 0; t < 16; t++) s += redA[tid * 16 + t];
        g_P[tJ][tI * 128 + tid] = s;
        if (!diag) {
            float s2 = 0.f;
#pragma unroll
            for (int t = 0; t < 16; t++) s2 += redB[tid * 16 + t];
            g_P[tI][tJ * 128 + tid] = s2;
        }
    }
}

// ---------------------------------------------------------------------------
// L[i] = log( sum over all 64 column-tile partials )   (fixed order)
// ---------------------------------------------------------------------------
__global__ void lse_kernel() {
    int i = blockIdx.x * blockDim.x + threadIdx.x;
    if (i >= B_N) return;
    float s = 0.f;
#pragma unroll
    for (int t = 0; t < NT; t++) s += g_P[t][i];
    g_L[i] = logf(s);
}

// ---------------------------------------------------------------------------
// rowloss[i] = (1/(cnt-1)) * sum over positives of log1p(exp(L_i - x))
// one warp per row; shuffle tree reduce (deterministic)
// ---------------------------------------------------------------------------
__global__ void pos_kernel() {
    int row = blockIdx.x * 8 + (threadIdx.x >> 5);
    int lane = threadIdx.x & 31;
    if (row >= B_N) return;
    int cnt = g_cnt[g_lab[row]];
    int rk = g_rank[row];
    float L = g_L[row];
    float s = 0.f;
    for (int k = lane; k < cnt; k += 32)
        if (k != rk)
            s += log1pf(expf(L - g_pos[(size_t)row * MAXP + k]));
#pragma unroll
    for (int o = 16; o; o >>= 1) s += __shfl_xor_sync(0xffffffffu, s, o);
    if (lane == 0) g_rowloss[row] = (cnt > 1) ? s / (float)(cnt - 1) : 0.f;
}

// ---------------------------------------------------------------------------
// final deterministic tree reduction
// ---------------------------------------------------------------------------
__global__ void reduce_kernel(float* out) {
    __shared__ float sm[1024];
    int t = threadIdx.x;
    float s = 0.f;
    for (int i = t; i < B_N; i += 1024) s += g_rowloss[i];
    sm[t] = s;
    __syncthreads();
    for (int o = 512; o; o >>= 1) {
        if (t < o) sm[t] += sm[t + o];
        __syncthreads();
    }
    if (t == 0) out[0] = sm[0] / (float)B_N;
}

// ---------------------------------------------------------------------------
extern "C" void kernel_launch(void* const* d_in, const int* in_sizes, int n_in,
                              void* d_out, int out_size) {
    const float* embeds;
    const int* labelsRaw;
    if (in_sizes[0] == B_N * D_K) {
        embeds = (const float*)d_in[0];
        labelsRaw = (const int*)d_in[1];
    } else {
        embeds = (const float*)d_in[1];
        labelsRaw = (const int*)d_in[0];
    }

    prep_kernel<<<1, 256>>>(labelsRaw);

    dim3 grid(NT, NT);
    gemm_kernel<<<grid, 256>>>(embeds);

    lse_kernel<<<32, 256>>>();
    pos_kernel<<<1024, 256>>>();
    reduce_kernel<<<1, 1024>>>((float*)d_out);
}

// round 14
// speedup vs baseline: 2.2027x; 2.2027x over previous
#include <cuda_runtime.h>
#include <cuda_bf16.h>
#include <math.h>
#include <stdint.h>

#define B_N 8192
#define D_K 512
#define NCLS 100
#define MAXP 256
#define NT 64                         // 8192/128 tiles per dim
#define KCHUNK 32
#define NCH (D_K / KCHUNK)            // 16
#define PADK 40                       // smem row stride in bf16 (80B) -> conflict-free frags
#define TILE_SB (128 * PADK * 2)      // 10240 B per smem tile
#define TILE_B32 (128 * (PADK / 2))   // 2560 b32 per tile
#define STAGE_B (4 * TILE_SB)         // Ahi,Alo,Bhi,Blo = 40960 B
#define INV_TEMP 14.285714285714286f

// -------- static scratch (no allocations allowed) --------
__device__ float g_P[NT][B_N];          // per-(colTile,row) partial exp sums (2 MB)
__device__ float g_pos[B_N * MAXP];     // same-label logits at class-rank slots (8 MB)
__device__ float g_L[B_N];
__device__ float g_rowloss[B_N];
__device__ int   g_lab[B_N];
__device__ int   g_rank[B_N];
__device__ int   g_cnt[NCLS];
// plain row-major bf16 hi/lo copies of embeds: [8192][512]
__device__ __nv_bfloat16 g_hi[B_N * D_K];   // 8 MB
__device__ __nv_bfloat16 g_lo[B_N * D_K];   // 8 MB

// ---------------- helpers (base-target PTX only: no 'a'-gated features) ----
__device__ __forceinline__ uint32_t smem_u32(const void* p) {
    uint32_t a;
    asm("{ .reg .u64 t; cvta.to.shared.u64 t, %1; cvt.u32.u64 %0, t; }" : "=r"(a) : "l"(p));
    return a;
}
__device__ __forceinline__ void cp16(void* dst_smem, const void* src) {
    uint32_t d = smem_u32(dst_smem);
    asm volatile("cp.async.cg.shared.global [%0], [%1], 16;" :: "r"(d), "l"(src) : "memory");
}
__device__ __forceinline__ void cp_commit() {
    asm volatile("cp.async.commit_group;" ::: "memory");
}
__device__ __forceinline__ void cp_wait1() {
    asm volatile("cp.async.wait_group 1;" ::: "memory");
}
__device__ __forceinline__ void cp_wait0() {
    asm volatile("cp.async.wait_group 0;" ::: "memory");
}
// m16n8k16 bf16 MMA, D accumulates in place (f32)
__device__ __forceinline__ void mma16816(float* d, const uint32_t* a, uint32_t b0, uint32_t b1) {
    asm volatile("mma.sync.aligned.m16n8k16.row.col.f32.bf16.bf16.f32 "
                 "{%0,%1,%2,%3}, {%4,%5,%6,%7}, {%8,%9}, {%0,%1,%2,%3};"
                 : "+f"(d[0]), "+f"(d[1]), "+f"(d[2]), "+f"(d[3])
                 : "r"(a[0]), "r"(a[1]), "r"(a[2]), "r"(a[3]), "r"(b0), "r"(b1));
}

// ---------------------------------------------------------------------------
// prep: parse labels (int32 or int64), per-class parallel rank assignment.
// ---------------------------------------------------------------------------
__global__ void prep_kernel(const int* __restrict__ raw) {
    __shared__ int sl[B_N];
    __shared__ int mode64;
    int tid = threadIdx.x;
    if (tid == 0) {
        int z = 1;
        for (int i = 1; i < 129; i += 2) if (raw[i] != 0) { z = 0; break; }
        mode64 = z;
    }
    __syncthreads();
    int m = mode64;
    for (int i = tid; i < B_N; i += blockDim.x) {
        int v = m ? raw[2 * i] : raw[i];
        sl[i] = v;
        g_lab[i] = v;
    }
    __syncthreads();
    if (tid < NCLS) {
        int c = tid, cnt = 0;
        for (int j = 0; j < B_N; j++) {
            if (sl[j] == c) { g_rank[j] = cnt; cnt++; }
        }
        g_cnt[c] = cnt;
    }
}

// ---------------------------------------------------------------------------
// convert: fp32 -> bf16 hi/lo, plain row-major layout.
// grid 2048 x 256, 4 bf16x2 pairs per thread.
// ---------------------------------------------------------------------------
__global__ void convert_kernel(const float* __restrict__ A) {
    int base = blockIdx.x * 256 + threadIdx.x;
#pragma unroll
    for (int it = 0; it < 4; it++) {
        int pe = base + it * (2048 * 256);          // pair index 0..2097151
        float2 v = *(const float2*)(A + (size_t)pe * 2);
        __nv_bfloat16 h0 = __float2bfloat16(v.x);
        __nv_bfloat16 h1 = __float2bfloat16(v.y);
        __nv_bfloat16 l0 = __float2bfloat16(v.x - __bfloat162float(h0));
        __nv_bfloat16 l1 = __float2bfloat16(v.y - __bfloat162float(h1));
        __nv_bfloat162 ph; ph.x = h0; ph.y = h1;
        __nv_bfloat162 pl; pl.x = l0; pl.y = l1;
        ((__nv_bfloat162*)g_hi)[pe] = ph;
        ((__nv_bfloat162*)g_lo)[pe] = pl;
    }
}

// ---------------------------------------------------------------------------
// HMMA bf16-split GEMM: tile (tI,tJ), tI<=tJ. 8 warps (4x2), warp tile 32x64.
// cp.async double-buffered K-chunks of 32. acc = hi*hi + hi*lo + lo*hi (fp32).
// Epilogue: exp/scatter from register accs -> smem e -> fixed-order sums.
// ---------------------------------------------------------------------------
__global__ void __launch_bounds__(256) gemm_kernel() {
    extern __shared__ char dyn[];
    __shared__ int lbI[128], lbJ[128], rkI[128], rkJ[128];

    int tJ = blockIdx.x, tI = blockIdx.y;
    if (tI > tJ) return;
    bool diag = (tI == tJ);

    int tid = threadIdx.x, wid = tid >> 5, lane = tid & 31;
    int g = lane >> 2, t = lane & 3;
    int warpM = wid & 3, warpN = wid >> 2;     // 4 x 2 warp grid

    if (tid < 128) {
        lbI[tid] = g_lab[tI * 128 + tid];
        rkI[tid] = g_rank[tI * 128 + tid];
        lbJ[tid] = g_lab[tJ * 128 + tid];
        rkJ[tid] = g_rank[tJ * 128 + tid];
    }
    __syncthreads();

    const char* Hb = (const char*)g_hi;
    const char* Lb = (const char*)g_lo;
    size_t rowI = (size_t)tI * 128, rowJ = (size_t)tJ * 128;

    // per-thread copy slots: idx = tid, tid+256 -> r = idx>>2, seg = idx&3
    int r0c = tid >> 2, s0c = tid & 3;
    int r1c = (tid + 256) >> 2, s1c = (tid + 256) & 3;

    // issue a chunk copy into stage s (4 tiles x 2 cp per thread = 8 cp.async)
    auto issue = [&](int c, int s) {
        char* st = dyn + s * STAGE_B;
        size_t kof = (size_t)c * KCHUNK * 2;     // byte offset of chunk in a row
#pragma unroll
        for (int q = 0; q < 2; q++) {
            int r = q ? r1c : r0c, sg = q ? s1c : s0c;
            uint32_t so = (uint32_t)r * (PADK * 2) + sg * 16;
            size_t goI = (rowI + r) * (D_K * 2) + kof + sg * 16;
            size_t goJ = (rowJ + r) * (D_K * 2) + kof + sg * 16;
            cp16(st + 0 * TILE_SB + so, Hb + goI);
            cp16(st + 1 * TILE_SB + so, Lb + goI);
            cp16(st + 2 * TILE_SB + so, Hb + goJ);
            cp16(st + 3 * TILE_SB + so, Lb + goJ);
        }
        cp_commit();
    };

    float acc[2][8][4];
#pragma unroll
    for (int mt = 0; mt < 2; mt++)
#pragma unroll
        for (int nt = 0; nt < 8; nt++)
#pragma unroll
            for (int p = 0; p < 4; p++) acc[mt][nt][p] = 0.f;

    issue(0, 0);

    for (int c = 0; c < NCH; c++) {
        int buf = c & 1;
        if (c + 1 < NCH) { issue(c + 1, buf ^ 1); cp_wait1(); }
        else cp_wait0();
        __syncthreads();

        const uint32_t* sAh = (const uint32_t*)(dyn + buf * STAGE_B);
        const uint32_t* sAl = sAh + TILE_B32;
        const uint32_t* sBh = sAl + TILE_B32;
        const uint32_t* sBl = sBh + TILE_B32;

#pragma unroll
        for (int ks = 0; ks < 2; ks++) {
            int kb = ks * 8;
            uint32_t ah[2][4], al[2][4];
#pragma unroll
            for (int mt = 0; mt < 2; mt++) {
                int ra = warpM * 32 + mt * 16 + g;
                int o0 = ra * (PADK / 2) + kb + t;
                int o1 = (ra + 8) * (PADK / 2) + kb + t;
                ah[mt][0] = sAh[o0];     ah[mt][1] = sAh[o1];
                ah[mt][2] = sAh[o0 + 4]; ah[mt][3] = sAh[o1 + 4];
                al[mt][0] = sAl[o0];     al[mt][1] = sAl[o1];
                al[mt][2] = sAl[o0 + 4]; al[mt][3] = sAl[o1 + 4];
            }
#pragma unroll
            for (int nt = 0; nt < 8; nt++) {
                int n = warpN * 64 + nt * 8 + g;
                int ob = n * (PADK / 2) + kb + t;
                uint32_t bh0 = sBh[ob], bh1 = sBh[ob + 4];
                uint32_t bl0 = sBl[ob], bl1 = sBl[ob + 4];
#pragma unroll
                for (int mt = 0; mt < 2; mt++) {
                    mma16816(acc[mt][nt], ah[mt], bh0, bh1);
                    mma16816(acc[mt][nt], ah[mt], bl0, bl1);
                    mma16816(acc[mt][nt], al[mt], bh0, bh1);
                }
            }
        }
        __syncthreads();   // done reading buf before chunk c+2 overwrites it
    }

    // -------- epilogue --------
    float* e = (float*)dyn;              // [128][129] fp32 (66KB < 80KB stages)
#pragma unroll
    for (int mt = 0; mt < 2; mt++) {
#pragma unroll
        for (int p = 0; p < 4; p++) {
            int i = warpM * 32 + mt * 16 + g + ((p >> 1) ? 8 : 0);
            int li = lbI[i];
            int gi = tI * 128 + i;
#pragma unroll
            for (int nt = 0; nt < 8; nt++) {
                int j = warpN * 64 + nt * 8 + t * 2 + (p & 1);
                float x = acc[mt][nt][p] * INV_TEMP;
                float ev = 0.f;
                if (li != lbJ[j]) {
                    ev = __expf(x);
                } else {
                    int gj = tJ * 128 + j;
                    if (gi != gj) {
                        g_pos[(size_t)gi * MAXP + rkJ[j]] = x;
                        if (!diag) g_pos[(size_t)gj * MAXP + rkI[i]] = x;
                    }
                }
                e[i * 129 + j] = ev;
            }
        }
    }
    __syncthreads();

    if (tid < 128) {
        float s = 0.f;
#pragma unroll 8
        for (int j = 0; j < 128; j++) s += e[tid * 129 + j];
        g_P[tJ][tI * 128 + tid] = s;
    } else if (!diag) {
        int j = tid - 128;
        float s = 0.f;
#pragma unroll 8
        for (int ii = 0; ii < 128; ii++) s += e[ii * 129 + j];
        g_P[tI][tJ * 128 + j] = s;
    }
}

// ---------------------------------------------------------------------------
__global__ void lse_kernel() {
    int i = blockIdx.x * blockDim.x + threadIdx.x;
    if (i >= B_N) return;
    float s = 0.f;
#pragma unroll
    for (int t = 0; t < NT; t++) s += g_P[t][i];
    g_L[i] = logf(s);
}

__global__ void pos_kernel() {
    int row = blockIdx.x * 8 + (threadIdx.x >> 5);
    int lane = threadIdx.x & 31;
    if (row >= B_N) return;
    int cnt = g_cnt[g_lab[row]];
    int rk = g_rank[row];
    float L = g_L[row];
    float s = 0.f;
    for (int k = lane; k < cnt; k += 32)
        if (k != rk)
            s += log1pf(expf(L - g_pos[(size_t)row * MAXP + k]));
#pragma unroll
    for (int o = 16; o; o >>= 1) s += __shfl_xor_sync(0xffffffffu, s, o);
    if (lane == 0) g_rowloss[row] = (cnt > 1) ? s / (float)(cnt - 1) : 0.f;
}

__global__ void reduce_kernel(float* out) {
    __shared__ float sm[1024];
    int t = threadIdx.x;
    float s = 0.f;
    for (int i = t; i < B_N; i += 1024) s += g_rowloss[i];
    sm[t] = s;
    __syncthreads();
    for (int o = 512; o; o >>= 1) {
        if (t < o) sm[t] += sm[t + o];
        __syncthreads();
    }
    if (t == 0) out[0] = sm[0] / (float)B_N;
}

// ---------------------------------------------------------------------------
extern "C" void kernel_launch(void* const* d_in, const int* in_sizes, int n_in,
                              void* d_out, int out_size) {
    const float* embeds;
    const int* labelsRaw;
    if (in_sizes[0] == B_N * D_K) {
        embeds = (const float*)d_in[0];
        labelsRaw = (const int*)d_in[1];
    } else {
        embeds = (const float*)d_in[1];
        labelsRaw = (const int*)d_in[0];
    }

    int dynBytes = 2 * STAGE_B;   // 81920
    cudaFuncSetAttribute(gemm_kernel, cudaFuncAttributeMaxDynamicSharedMemorySize, dynBytes);

    prep_kernel<<<1, 256>>>(labelsRaw);
    convert_kernel<<<2048, 256>>>(embeds);

    dim3 grid(NT, NT);
    gemm_kernel<<<grid, 256, dynBytes>>>();

    lse_kernel<<<32, 256>>>();
    pos_kernel<<<1024, 256>>>();
    reduce_kernel<<<1, 1024>>>((float*)d_out);
}